// round 3
// baseline (speedup 1.0000x reference)
#include <cuda_runtime.h>
#include <math.h>

// Problem constants
#define DD   512
#define SS   512
#define BB   32
#define WW   3
#define NTOK (BB*SS)          // 16384 tokens
#define NELEM ((size_t)NTOK*DD)

// ---------------------------------------------------------------------------
// Scratch (allocation-free: __device__ globals, zero-init bss)
// ---------------------------------------------------------------------------
__device__ float g_xf[NELEM];   // forward stream state
__device__ float g_xb[NELEM];   // backward stream state
__device__ float g_y [NELEM];   // window-sum (residual input)
__device__ float g_z [NELEM];   // layernorm output
__device__ float g_h [NELEM];   // hidden (relu) activations

// ---------------------------------------------------------------------------
// Kernel 1: fused sliding-window weighted sum + LayerNorm (unbiased std)
//   y[t,d]  = sum_{k=0..3} w[k] * padded[t + offset + k, d]
//   z       = g*(y-mean)/(std_ddof1 + 1e-6) + beta
// One block per token, 256 threads, 2 elements/thread.
// ---------------------------------------------------------------------------
__global__ void winln_kernel(const float* __restrict__ x0,
                             const float* __restrict__ padf,
                             const float* __restrict__ padb,
                             const float* __restrict__ wv,
                             const float* __restrict__ gamma,
                             const float* __restrict__ beta,
                             int offset, int use_x0, int is_fwd)
{
    const float* __restrict__ xin = use_x0 ? x0 : (is_fwd ? g_xf : g_xb);

    int token = blockIdx.x;                 // b*S + t
    int b = token >> 9;
    int t = token & (SS - 1);
    int tid = threadIdx.x;

    float wk0 = wv[0], wk1 = wv[1], wk2 = wv[2], wk3 = wv[3];
    float wk[4] = {wk0, wk1, wk2, wk3};

    float yv[2];
    float sum = 0.f, sq = 0.f;

#pragma unroll
    for (int e = 0; e < 2; e++) {
        int d = tid + e * 256;
        float y = 0.f;
#pragma unroll
        for (int k = 0; k < 4; k++) {
            int j = t + offset + k;         // padded index in [0, S+2W)
            float v;
            if (j < WW)             v = padf[j * DD + d];
            else if (j < WW + SS)   v = xin[((size_t)b * SS + (j - WW)) * DD + d];
            else                    v = padb[(j - WW - SS) * DD + d];
            y = fmaf(wk[k], v, y);
        }
        yv[e] = y;
        sum += y;
        sq  = fmaf(y, y, sq);
    }

    // block reduction (8 warps)
#pragma unroll
    for (int o = 16; o > 0; o >>= 1) {
        sum += __shfl_down_sync(0xffffffffu, sum, o);
        sq  += __shfl_down_sync(0xffffffffu, sq , o);
    }
    __shared__ float s1[8], s2[8];
    int wid = tid >> 5, lane = tid & 31;
    if (lane == 0) { s1[wid] = sum; s2[wid] = sq; }
    __syncthreads();
    float tot = 0.f, tot2 = 0.f;
#pragma unroll
    for (int i = 0; i < 8; i++) { tot += s1[i]; tot2 += s2[i]; }

    float mean = tot * (1.0f / DD);
    float var  = (tot2 - tot * mean) * (1.0f / (DD - 1));   // unbiased (ddof=1)
    var = fmaxf(var, 0.f);
    float inv = 1.0f / (sqrtf(var) + 1e-6f);

#pragma unroll
    for (int e = 0; e < 2; e++) {
        int d = tid + e * 256;
        size_t idx = (size_t)token * DD + d;
        g_y[idx] = yv[e];
        g_z[idx] = fmaf(gamma[d], (yv[e] - mean) * inv, beta[d]);
    }
}

// ---------------------------------------------------------------------------
// Kernel 2: SGEMM  [16384 x 512] @ [512 x 512], 128x128x8 tile, 8x8/thread.
//   MODE 0:  h = relu(z @ W1 + b1)            (A = g_z, C = g_h)
//   MODE 1:  x' = y + h @ W2 + b2             (A = g_h, C = g_xf|g_xb,
//            also stores x' into strided d_out slice)
// ---------------------------------------------------------------------------
#define BM 128
#define BN 128
#define BK 8
#define GK 512

template<int MODE>
__global__ void __launch_bounds__(256, 2)
gemm_kernel(const float* __restrict__ Bmat,
            const float* __restrict__ bias,
            float* __restrict__ outp,       // d_out (MODE 1), unused MODE 0
            long long outbase,              // (l*NTOK)*1024 + off
            int is_fwd)
{
    const float* __restrict__ A = (MODE == 0) ? g_z : g_h;
    float* __restrict__ C       = (MODE == 0) ? g_h : (is_fwd ? g_xf : g_xb);

    __shared__ float As[BK][BM + 4];
    __shared__ float Bs[BK][BN];

    int bx = blockIdx.x;        // N tile (0..3)
    int by = blockIdx.y;        // M tile (0..127)
    int tid = threadIdx.x;
    int tx = tid & 15;
    int ty = tid >> 4;

    const float* Ab = A + (size_t)by * BM * GK;
    const float* Bb = Bmat + bx * BN;

    int ar = tid >> 1;             // 0..127 (A row in tile)
    int ac = (tid & 1) * 4;        // k sub-chunk 0 or 4
    int br = tid >> 5;             // 0..7   (B row in tile)
    int bc = (tid & 31) * 4;       // 0..124 (B col in tile)

    float acc[8][8];
#pragma unroll
    for (int i = 0; i < 8; i++)
#pragma unroll
        for (int j = 0; j < 8; j++) acc[i][j] = 0.f;

    for (int k0 = 0; k0 < GK; k0 += BK) {
        float4 av = *(const float4*)(Ab + (size_t)ar * GK + k0 + ac);
        As[ac + 0][ar] = av.x;
        As[ac + 1][ar] = av.y;
        As[ac + 2][ar] = av.z;
        As[ac + 3][ar] = av.w;
        float4 bv = *(const float4*)(Bb + (size_t)(k0 + br) * 512 + bc);
        *(float4*)(&Bs[br][bc]) = bv;
        __syncthreads();

#pragma unroll
        for (int k = 0; k < BK; k++) {
            float a[8], b[8];
            *(float4*)(a)     = *(const float4*)(&As[k][ty * 4]);
            *(float4*)(a + 4) = *(const float4*)(&As[k][ty * 4 + 64]);
            *(float4*)(b)     = *(const float4*)(&Bs[k][tx * 4]);
            *(float4*)(b + 4) = *(const float4*)(&Bs[k][tx * 4 + 64]);
#pragma unroll
            for (int i = 0; i < 8; i++)
#pragma unroll
                for (int j = 0; j < 8; j++)
                    acc[i][j] = fmaf(a[i], b[j], acc[i][j]);
        }
        __syncthreads();
    }

    // epilogue
#pragma unroll
    for (int i = 0; i < 8; i++) {
        int row = by * BM + ((i < 4) ? (ty * 4 + i) : (64 + ty * 4 + (i - 4)));
#pragma unroll
        for (int h2 = 0; h2 < 2; h2++) {
            int col = bx * BN + tx * 4 + h2 * 64;
            float4 bsv = *(const float4*)(bias + col);
            float4 v;
            v.x = acc[i][h2 * 4 + 0] + bsv.x;
            v.y = acc[i][h2 * 4 + 1] + bsv.y;
            v.z = acc[i][h2 * 4 + 2] + bsv.z;
            v.w = acc[i][h2 * 4 + 3] + bsv.w;
            if (MODE == 0) {
                v.x = fmaxf(v.x, 0.f); v.y = fmaxf(v.y, 0.f);
                v.z = fmaxf(v.z, 0.f); v.w = fmaxf(v.w, 0.f);
                *(float4*)(C + (size_t)row * 512 + col) = v;
            } else {
                float4 rv = *(const float4*)(g_y + (size_t)row * 512 + col);
                v.x += rv.x; v.y += rv.y; v.z += rv.z; v.w += rv.w;
                *(float4*)(C + (size_t)row * 512 + col) = v;
                *(float4*)(outp + (size_t)outbase + (size_t)row * 1024 + col) = v;
            }
        }
    }
}

// ---------------------------------------------------------------------------
// Launch: 3 layers x 2 streams x (winln, gemm1, gemm2) = 18 launches,
// all on the capture stream, no sync, no alloc.
// ---------------------------------------------------------------------------
extern "C" void kernel_launch(void* const* d_in, const int* in_sizes, int n_in,
                              void* d_out, int out_size)
{
    const float* x       = (const float*)d_in[0];
    const float* fwd_pad = (const float*)d_in[1];
    const float* bwd_pad = (const float*)d_in[2];
    const float* fwd_w   = (const float*)d_in[3];
    const float* bwd_w   = (const float*)d_in[4];
    const float* fwd_w1  = (const float*)d_in[5];
    const float* fwd_b1  = (const float*)d_in[6];
    const float* fwd_w2  = (const float*)d_in[7];
    const float* fwd_b2  = (const float*)d_in[8];
    const float* fwd_g   = (const float*)d_in[9];
    const float* fwd_be  = (const float*)d_in[10];
    const float* bwd_w1  = (const float*)d_in[11];
    const float* bwd_b1  = (const float*)d_in[12];
    const float* bwd_w2  = (const float*)d_in[13];
    const float* bwd_b2  = (const float*)d_in[14];
    const float* bwd_g   = (const float*)d_in[15];
    const float* bwd_be  = (const float*)d_in[16];
    float* out = (float*)d_out;

    dim3 ggrid(4, 128);   // N tiles x M tiles

    for (int l = 0; l < 3; l++) {
        const float* pf = fwd_pad + (size_t)l * WW * DD;
        const float* pb = bwd_pad + (size_t)l * WW * DD;
        long long obase = (long long)l * NTOK * 1024;
        int use_x0 = (l == 0) ? 1 : 0;

        // ---- forward stream ----
        winln_kernel<<<NTOK, 256>>>(x, pf, pb,
                                    fwd_w + l * (WW + 1),
                                    fwd_g + l * DD, fwd_be + l * DD,
                                    /*offset=*/0, use_x0, /*is_fwd=*/1);
        gemm_kernel<0><<<ggrid, 256>>>(fwd_w1 + (size_t)l * DD * DD,
                                       fwd_b1 + l * DD, nullptr, 0, 1);
        gemm_kernel<1><<<ggrid, 256>>>(fwd_w2 + (size_t)l * DD * DD,
                                       fwd_b2 + l * DD, out, obase + 0, 1);

        // ---- backward stream ----
        winln_kernel<<<NTOK, 256>>>(x, pf, pb,
                                    bwd_w + l * (WW + 1),
                                    bwd_g + l * DD, bwd_be + l * DD,
                                    /*offset=*/WW, use_x0, /*is_fwd=*/0);
        gemm_kernel<0><<<ggrid, 256>>>(bwd_w1 + (size_t)l * DD * DD,
                                       bwd_b1 + l * DD, nullptr, 0, 0);
        gemm_kernel<1><<<ggrid, 256>>>(bwd_w2 + (size_t)l * DD * DD,
                                       bwd_b2 + l * DD, out, obase + 512, 0);
    }
}

// round 6
// speedup vs baseline: 1.4488x; 1.4488x over previous
#include <cuda_runtime.h>
#include <mma.h>
#include <math.h>
#include <stdint.h>

using namespace nvcuda;

// Problem constants
#define DD   512
#define SS   512
#define BB   32
#define WW   3
#define NTOK (BB*SS)          // 16384 tokens
#define NELEM ((size_t)NTOK*DD)

// ---------------------------------------------------------------------------
// Scratch (allocation-free: __device__ globals)
// ---------------------------------------------------------------------------
__device__ float g_xf[NELEM];   // forward stream state (fp32)
__device__ float g_xb[NELEM];   // backward stream state (fp32)
__device__ float g_y [NELEM];   // window-sum residual (fp32)
__device__ float g_z [NELEM];   // layernorm output (tf32-rounded)
__device__ float g_h [NELEM];   // relu hidden (tf32-rounded)
__device__ float g_wt[12 * DD * DD];  // tf32-rounded weights, [K,N] row-major

// ---------------------------------------------------------------------------
// Helpers
// ---------------------------------------------------------------------------
__device__ __forceinline__ uint32_t smem_u32(const void* p) {
    uint32_t a;
    asm("{ .reg .u64 t; cvta.to.shared.u64 t, %1; cvt.u32.u64 %0, t; }" : "=r"(a) : "l"(p));
    return a;
}
__device__ __forceinline__ float to_tf32(float x) {
    uint32_t r;
    asm("cvt.rna.tf32.f32 %0, %1;" : "=r"(r) : "f"(x));
    return __uint_as_float(r);
}
__device__ __forceinline__ void cp16(uint32_t s, const void* g) {
    asm volatile("cp.async.ca.shared.global [%0], [%1], 16;" :: "r"(s), "l"(g) : "memory");
}
#define CP_COMMIT() asm volatile("cp.async.commit_group;" ::: "memory")
#define CP_WAIT(N)  asm volatile("cp.async.wait_group %0;" :: "n"(N) : "memory")

// ---------------------------------------------------------------------------
// Prep: tf32-round the 12 weight matrices (no transpose; already [K,N])
// widx = l*4 + {0:fw1, 1:fw2, 2:bw1, 3:bw2}
// ---------------------------------------------------------------------------
__global__ void prep_kernel(const float* __restrict__ fw1,
                            const float* __restrict__ fw2,
                            const float* __restrict__ bw1,
                            const float* __restrict__ bw2)
{
    int widx = blockIdx.y;
    int l = widx >> 2, which = widx & 3;
    const float* src = (which == 0 ? fw1 : which == 1 ? fw2 : which == 2 ? bw1 : bw2)
                       + (size_t)l * DD * DD;
    float* dst = g_wt + (size_t)widx * DD * DD;
    int i4 = blockIdx.x * 256 + threadIdx.x;     // float4 index, 65536 per matrix
    float4 v = *(const float4*)(src + (size_t)i4 * 4);
    v.x = to_tf32(v.x); v.y = to_tf32(v.y); v.z = to_tf32(v.z); v.w = to_tf32(v.w);
    *(float4*)(dst + (size_t)i4 * 4) = v;
}

// ---------------------------------------------------------------------------
// Kernel 1: fused window-sum + LayerNorm. 1 token/block, 128 threads, float4.
// Stores y (fp32) and z (tf32-rounded).
// ---------------------------------------------------------------------------
__global__ void winln_kernel(const float* __restrict__ x0,
                             const float* __restrict__ padf,
                             const float* __restrict__ padb,
                             const float* __restrict__ wv,
                             const float* __restrict__ gamma,
                             const float* __restrict__ beta,
                             int offset, int use_x0, int is_fwd)
{
    const float* __restrict__ xin = use_x0 ? x0 : (is_fwd ? g_xf : g_xb);

    int token = blockIdx.x;
    int b = token >> 9;
    int t = token & (SS - 1);
    int tid = threadIdx.x;
    int d = tid * 4;

    float wk[4] = {wv[0], wv[1], wv[2], wv[3]};
    int j0 = t + offset;

    float4 acc = make_float4(0.f, 0.f, 0.f, 0.f);
    if (j0 >= WW && j0 + 3 < WW + SS) {
        const float* p = xin + ((size_t)(b * SS + (j0 - WW))) * DD + d;
#pragma unroll
        for (int k = 0; k < 4; k++) {
            float4 v = *(const float4*)(p + (size_t)k * DD);
            acc.x = fmaf(wk[k], v.x, acc.x);
            acc.y = fmaf(wk[k], v.y, acc.y);
            acc.z = fmaf(wk[k], v.z, acc.z);
            acc.w = fmaf(wk[k], v.w, acc.w);
        }
    } else {
#pragma unroll
        for (int k = 0; k < 4; k++) {
            int j = j0 + k;
            float4 v;
            if (j < WW)           v = *(const float4*)(padf + (size_t)j * DD + d);
            else if (j < WW + SS) v = *(const float4*)(xin + ((size_t)b * SS + (j - WW)) * DD + d);
            else                  v = *(const float4*)(padb + (size_t)(j - WW - SS) * DD + d);
            acc.x = fmaf(wk[k], v.x, acc.x);
            acc.y = fmaf(wk[k], v.y, acc.y);
            acc.z = fmaf(wk[k], v.z, acc.z);
            acc.w = fmaf(wk[k], v.w, acc.w);
        }
    }

    float sum = acc.x + acc.y + acc.z + acc.w;
    float sq  = acc.x * acc.x + acc.y * acc.y + acc.z * acc.z + acc.w * acc.w;
#pragma unroll
    for (int o = 16; o > 0; o >>= 1) {
        sum += __shfl_down_sync(0xffffffffu, sum, o);
        sq  += __shfl_down_sync(0xffffffffu, sq , o);
    }
    __shared__ float s1[4], s2[4];
    int wid = tid >> 5, lane = tid & 31;
    if (lane == 0) { s1[wid] = sum; s2[wid] = sq; }
    __syncthreads();
    float tot  = s1[0] + s1[1] + s1[2] + s1[3];
    float tot2 = s2[0] + s2[1] + s2[2] + s2[3];

    float mean = tot * (1.0f / DD);
    float var  = (tot2 - tot * mean) * (1.0f / (DD - 1));
    var = fmaxf(var, 0.f);
    float inv = 1.0f / (sqrtf(var) + 1e-6f);

    size_t idx = (size_t)token * DD + d;
    float4 gm = *(const float4*)(gamma + d);
    float4 bt = *(const float4*)(beta + d);
    float4 z;
    z.x = to_tf32(fmaf(gm.x, (acc.x - mean) * inv, bt.x));
    z.y = to_tf32(fmaf(gm.y, (acc.y - mean) * inv, bt.y));
    z.z = to_tf32(fmaf(gm.z, (acc.z - mean) * inv, bt.z));
    z.w = to_tf32(fmaf(gm.w, (acc.w - mean) * inv, bt.w));
    *(float4*)(g_y + idx) = acc;
    *(float4*)(g_z + idx) = z;
}

// ---------------------------------------------------------------------------
// Kernel 2: wmma tf32 GEMM  [16384 x 512] @ W[512(k) x 512(n)]
//   CTA tile 128x128, K-chunk 32, cp.async double-buffered.
//   8 warps: warp_m = wid>>1 (4), warp_n = wid&1 (2); per warp 32x64 = 2x4 frags.
//   MODE 0: h = tf32(relu(z @ W1 + b1))
//   MODE 1: x' = y + h @ W2 + b2   (+ strided store to d_out)
// ---------------------------------------------------------------------------
#define BM 128
#define BN 128
#define BK 32
#define ASTRIDE 36            // floats; 144B rows (16B-aligned)
#define BSTRIDE 132           // floats; 528B rows
#define CSTRIDE 136           // floats; 544B rows
#define A_FLOATS (BM * ASTRIDE)          // 4608
#define B_FLOATS (BK * BSTRIDE)          // 4224
#define SMEM_FLOATS (2 * A_FLOATS + 2 * B_FLOATS)  // 17664 (Cs: 128*136=17408 fits)
#define SMEM_BYTES  (SMEM_FLOATS * 4)              // 70656

template<int MODE>
__global__ void __launch_bounds__(256, 2)
gemm_kernel(int widx,
            const float* __restrict__ bias,
            float* __restrict__ outp,
            long long outbase,
            int is_fwd)
{
    extern __shared__ float sm[];
    float* As[2] = { sm, sm + A_FLOATS };
    float* Bs[2] = { sm + 2 * A_FLOATS, sm + 2 * A_FLOATS + B_FLOATS };
    float* Cs = sm;

    const float* __restrict__ A  = (MODE == 0) ? g_z : g_h;
    const float* __restrict__ Wm = g_wt + (size_t)widx * DD * DD;
    float* __restrict__ C        = (MODE == 0) ? g_h : (is_fwd ? g_xf : g_xb);

    int tid = threadIdx.x;
    int n0 = blockIdx.x * BN;
    int m0 = blockIdx.y * BM;

    int warp = tid >> 5;
    int warp_m = warp >> 1;      // 0..3 -> rows warp_m*32
    int warp_n = warp & 1;       // 0..1 -> cols warp_n*64

    // per-thread staging indices (4 float4 each for A and B per chunk)
    int arow[4], ac4[4], brow[4], bc4[4];
#pragma unroll
    for (int i = 0; i < 4; i++) {
        int idx = tid + i * 256;
        arow[i] = idx >> 3;  ac4[i] = idx & 7;     // A: 128 rows x 8 float4
        brow[i] = idx >> 5;  bc4[i] = idx & 31;    // B: 32 rows x 32 float4
    }

    wmma::fragment<wmma::accumulator, 16, 16, 8, float> acc[2][4];
#pragma unroll
    for (int i = 0; i < 2; i++)
#pragma unroll
        for (int j = 0; j < 4; j++) wmma::fill_fragment(acc[i][j], 0.f);

    // issue chunk 0
    {
        uint32_t a0 = smem_u32(As[0]), b0 = smem_u32(Bs[0]);
#pragma unroll
        for (int i = 0; i < 4; i++) {
            cp16(a0 + (arow[i] * ASTRIDE + ac4[i] * 4) * 4,
                 A + (size_t)(m0 + arow[i]) * DD + ac4[i] * 4);
            cp16(b0 + (brow[i] * BSTRIDE + bc4[i] * 4) * 4,
                 Wm + (size_t)brow[i] * DD + n0 + bc4[i] * 4);
        }
        CP_COMMIT();
    }

    const int NCH = DD / BK;   // 16
    for (int c = 0; c < NCH; c++) {
        int cur = c & 1, nxt = cur ^ 1;
        if (c + 1 < NCH) {
            int k0 = (c + 1) * BK;
            uint32_t an = smem_u32(As[nxt]), bn = smem_u32(Bs[nxt]);
#pragma unroll
            for (int i = 0; i < 4; i++) {
                cp16(an + (arow[i] * ASTRIDE + ac4[i] * 4) * 4,
                     A + (size_t)(m0 + arow[i]) * DD + k0 + ac4[i] * 4);
                cp16(bn + (brow[i] * BSTRIDE + bc4[i] * 4) * 4,
                     Wm + (size_t)(k0 + brow[i]) * DD + n0 + bc4[i] * 4);
            }
            CP_COMMIT();
            CP_WAIT(1);
        } else {
            CP_WAIT(0);
        }
        __syncthreads();

        const float* Ab = As[cur];
        const float* Bb = Bs[cur];
#pragma unroll
        for (int ks = 0; ks < 4; ks++) {
            wmma::fragment<wmma::matrix_a, 16, 16, 8, wmma::precision::tf32, wmma::row_major> fa[2];
            wmma::fragment<wmma::matrix_b, 16, 16, 8, wmma::precision::tf32, wmma::row_major> fb[4];
#pragma unroll
            for (int i = 0; i < 2; i++)
                wmma::load_matrix_sync(fa[i], Ab + (warp_m * 32 + i * 16) * ASTRIDE + ks * 8, ASTRIDE);
#pragma unroll
            for (int j = 0; j < 4; j++)
                wmma::load_matrix_sync(fb[j], Bb + (ks * 8) * BSTRIDE + warp_n * 64 + j * 16, BSTRIDE);
#pragma unroll
            for (int i = 0; i < 2; i++)
#pragma unroll
                for (int j = 0; j < 4; j++)
                    wmma::mma_sync(acc[i][j], fa[i], fb[j], acc[i][j]);
        }
        __syncthreads();
    }

    // stage accumulators to smem (reuses A/B buffers; all reads done)
#pragma unroll
    for (int i = 0; i < 2; i++)
#pragma unroll
        for (int j = 0; j < 4; j++)
            wmma::store_matrix_sync(Cs + (warp_m * 32 + i * 16) * CSTRIDE + warp_n * 64 + j * 16,
                                    acc[i][j], CSTRIDE, wmma::mem_row_major);
    __syncthreads();

    // epilogue: 2 threads per row, 16 float4 each
    int row  = tid >> 1;
    int half = tid & 1;
    int grow = m0 + row;
    const float* crow = Cs + row * CSTRIDE + half * 64;
#pragma unroll
    for (int v = 0; v < 16; v++) {
        int col = n0 + half * 64 + v * 4;
        float4 o = *(const float4*)(crow + v * 4);
        float4 bs = *(const float4*)(bias + col);
        o.x += bs.x; o.y += bs.y; o.z += bs.z; o.w += bs.w;
        if (MODE == 0) {
            o.x = to_tf32(fmaxf(o.x, 0.f)); o.y = to_tf32(fmaxf(o.y, 0.f));
            o.z = to_tf32(fmaxf(o.z, 0.f)); o.w = to_tf32(fmaxf(o.w, 0.f));
            *(float4*)(C + (size_t)grow * DD + col) = o;
        } else {
            float4 rv = *(const float4*)(g_y + (size_t)grow * DD + col);
            o.x += rv.x; o.y += rv.y; o.z += rv.z; o.w += rv.w;
            *(float4*)(C + (size_t)grow * DD + col) = o;
            *(float4*)(outp + (size_t)outbase + (size_t)grow * 1024 + col) = o;
        }
    }
}

// ---------------------------------------------------------------------------
// Launch: prep + 3 layers x 2 streams x (winln, gemm1, gemm2)
// ---------------------------------------------------------------------------
extern "C" void kernel_launch(void* const* d_in, const int* in_sizes, int n_in,
                              void* d_out, int out_size)
{
    const float* x       = (const float*)d_in[0];
    const float* fwd_pad = (const float*)d_in[1];
    const float* bwd_pad = (const float*)d_in[2];
    const float* fwd_w   = (const float*)d_in[3];
    const float* bwd_w   = (const float*)d_in[4];
    const float* fwd_w1  = (const float*)d_in[5];
    const float* fwd_b1  = (const float*)d_in[6];
    const float* fwd_w2  = (const float*)d_in[7];
    const float* fwd_b2  = (const float*)d_in[8];
    const float* fwd_g   = (const float*)d_in[9];
    const float* fwd_be  = (const float*)d_in[10];
    const float* bwd_w1  = (const float*)d_in[11];
    const float* bwd_b1  = (const float*)d_in[12];
    const float* bwd_w2  = (const float*)d_in[13];
    const float* bwd_b2  = (const float*)d_in[14];
    const float* bwd_g   = (const float*)d_in[15];
    const float* bwd_be  = (const float*)d_in[16];
    float* out = (float*)d_out;

    static int smem_set = 0;
    if (!smem_set) {
        cudaFuncSetAttribute(gemm_kernel<0>, cudaFuncAttributeMaxDynamicSharedMemorySize, SMEM_BYTES);
        cudaFuncSetAttribute(gemm_kernel<1>, cudaFuncAttributeMaxDynamicSharedMemorySize, SMEM_BYTES);
        smem_set = 1;
    }

    prep_kernel<<<dim3(256, 12), 256>>>(fwd_w1, fwd_w2, bwd_w1, bwd_w2);

    dim3 ggrid(4, 128);   // N tiles x M tiles

    for (int l = 0; l < 3; l++) {
        const float* pf = fwd_pad + (size_t)l * WW * DD;
        const float* pb = bwd_pad + (size_t)l * WW * DD;
        long long obase = (long long)l * NTOK * 1024;
        int use_x0 = (l == 0) ? 1 : 0;

        // ---- forward stream ----
        winln_kernel<<<NTOK, 128>>>(x, pf, pb, fwd_w + l * (WW + 1),
                                    fwd_g + l * DD, fwd_be + l * DD, 0, use_x0, 1);
        gemm_kernel<0><<<ggrid, 256, SMEM_BYTES>>>(l * 4 + 0, fwd_b1 + l * DD, nullptr, 0, 1);
        gemm_kernel<1><<<ggrid, 256, SMEM_BYTES>>>(l * 4 + 1, fwd_b2 + l * DD, out, obase + 0, 1);

        // ---- backward stream ----
        winln_kernel<<<NTOK, 128>>>(x, pf, pb, bwd_w + l * (WW + 1),
                                    bwd_g + l * DD, bwd_be + l * DD, WW, use_x0, 0);
        gemm_kernel<0><<<ggrid, 256, SMEM_BYTES>>>(l * 4 + 2, bwd_b1 + l * DD, nullptr, 0, 0);
        gemm_kernel<1><<<ggrid, 256, SMEM_BYTES>>>(l * 4 + 3, bwd_b2 + l * DD, out, obase + 512, 0);
    }
}

// round 7
// speedup vs baseline: 1.5850x; 1.0940x over previous
#include <cuda_runtime.h>
#include <mma.h>
#include <math.h>
#include <stdint.h>

using namespace nvcuda;

// Problem constants
#define DD   512
#define SS   512
#define BB   32
#define WW   3
#define NTOK (BB*SS)          // 16384 tokens per stream
#define NELEM ((size_t)NTOK*DD)

// ---------------------------------------------------------------------------
// Scratch (allocation-free). Row index = half*NTOK + token (half 0=fwd,1=bwd).
// ---------------------------------------------------------------------------
__device__ float g_state[2 * NELEM];  // stream states (fp32)
__device__ float g_y [2 * NELEM];     // window-sum residual (fp32)
__device__ float g_z [2 * NELEM];     // layernorm output (tf32-rounded)
__device__ float g_h [2 * NELEM];     // relu hidden (tf32-rounded)
__device__ float g_wt[12 * DD * DD];  // tf32-rounded weights, [K,N] row-major

// ---------------------------------------------------------------------------
// Helpers
// ---------------------------------------------------------------------------
__device__ __forceinline__ uint32_t smem_u32(const void* p) {
    uint32_t a;
    asm("{ .reg .u64 t; cvta.to.shared.u64 t, %1; cvt.u32.u64 %0, t; }" : "=r"(a) : "l"(p));
    return a;
}
__device__ __forceinline__ float to_tf32(float x) {
    uint32_t r;
    asm("cvt.rna.tf32.f32 %0, %1;" : "=r"(r) : "f"(x));
    return __uint_as_float(r);
}
__device__ __forceinline__ void cp16(uint32_t s, const void* g) {
    asm volatile("cp.async.cg.shared.global [%0], [%1], 16;" :: "r"(s), "l"(g) : "memory");
}
#define CP_COMMIT() asm volatile("cp.async.commit_group;" ::: "memory")
#define CP_WAIT(N)  asm volatile("cp.async.wait_group %0;" :: "n"(N) : "memory")

// ---------------------------------------------------------------------------
// Prep: tf32-round the 12 weight matrices. widx = l*4 + {fw1,fw2,bw1,bw2}
// ---------------------------------------------------------------------------
__global__ void prep_kernel(const float* __restrict__ fw1,
                            const float* __restrict__ fw2,
                            const float* __restrict__ bw1,
                            const float* __restrict__ bw2)
{
    int widx = blockIdx.y;
    int l = widx >> 2, which = widx & 3;
    const float* src = (which == 0 ? fw1 : which == 1 ? fw2 : which == 2 ? bw1 : bw2)
                       + (size_t)l * DD * DD;
    float* dst = g_wt + (size_t)widx * DD * DD;
    int i4 = blockIdx.x * 256 + threadIdx.x;
    float4 v = *(const float4*)(src + (size_t)i4 * 4);
    v.x = to_tf32(v.x); v.y = to_tf32(v.y); v.z = to_tf32(v.z); v.w = to_tf32(v.w);
    *(float4*)(dst + (size_t)i4 * 4) = v;
}

// ---------------------------------------------------------------------------
// Kernel 1: fused window-sum + LayerNorm, BOTH streams in one launch.
// grid = 2*NTOK blocks; block >= NTOK -> backward half.
// ---------------------------------------------------------------------------
__global__ void winln_kernel(const float* __restrict__ x0,
                             const float* __restrict__ padf,
                             const float* __restrict__ padb,
                             const float* __restrict__ wvf,
                             const float* __restrict__ wvb,
                             const float* __restrict__ gf,
                             const float* __restrict__ bef,
                             const float* __restrict__ gb,
                             const float* __restrict__ beb,
                             int use_x0)
{
    int gtok  = blockIdx.x;
    int half  = gtok >> 14;              // 0 fwd, 1 bwd
    int token = gtok & (NTOK - 1);
    int b = token >> 9;
    int t = token & (SS - 1);
    int tid = threadIdx.x;
    int d = tid * 4;

    const float* __restrict__ xin = use_x0 ? x0 : (g_state + (size_t)half * NELEM);
    const float* __restrict__ wv    = half ? wvb : wvf;
    const float* __restrict__ gamma = half ? gb  : gf;
    const float* __restrict__ beta  = half ? beb : bef;
    int offset = half ? WW : 0;

    float wk[4] = {wv[0], wv[1], wv[2], wv[3]};
    int j0 = t + offset;

    float4 acc = make_float4(0.f, 0.f, 0.f, 0.f);
    if (j0 >= WW && j0 + 3 < WW + SS) {
        const float* p = xin + ((size_t)(b * SS + (j0 - WW))) * DD + d;
#pragma unroll
        for (int k = 0; k < 4; k++) {
            float4 v = *(const float4*)(p + (size_t)k * DD);
            acc.x = fmaf(wk[k], v.x, acc.x);
            acc.y = fmaf(wk[k], v.y, acc.y);
            acc.z = fmaf(wk[k], v.z, acc.z);
            acc.w = fmaf(wk[k], v.w, acc.w);
        }
    } else {
#pragma unroll
        for (int k = 0; k < 4; k++) {
            int j = j0 + k;
            float4 v;
            if (j < WW)           v = *(const float4*)(padf + (size_t)j * DD + d);
            else if (j < WW + SS) v = *(const float4*)(xin + ((size_t)b * SS + (j - WW)) * DD + d);
            else                  v = *(const float4*)(padb + (size_t)(j - WW - SS) * DD + d);
            acc.x = fmaf(wk[k], v.x, acc.x);
            acc.y = fmaf(wk[k], v.y, acc.y);
            acc.z = fmaf(wk[k], v.z, acc.z);
            acc.w = fmaf(wk[k], v.w, acc.w);
        }
    }

    float sum = acc.x + acc.y + acc.z + acc.w;
    float sq  = acc.x * acc.x + acc.y * acc.y + acc.z * acc.z + acc.w * acc.w;
#pragma unroll
    for (int o = 16; o > 0; o >>= 1) {
        sum += __shfl_down_sync(0xffffffffu, sum, o);
        sq  += __shfl_down_sync(0xffffffffu, sq , o);
    }
    __shared__ float s1[4], s2[4];
    int wid = tid >> 5, lane = tid & 31;
    if (lane == 0) { s1[wid] = sum; s2[wid] = sq; }
    __syncthreads();
    float tot  = s1[0] + s1[1] + s1[2] + s1[3];
    float tot2 = s2[0] + s2[1] + s2[2] + s2[3];

    float mean = tot * (1.0f / DD);
    float var  = (tot2 - tot * mean) * (1.0f / (DD - 1));
    var = fmaxf(var, 0.f);
    float inv = 1.0f / (sqrtf(var) + 1e-6f);

    size_t idx = (size_t)gtok * DD + d;
    float4 gm = *(const float4*)(gamma + d);
    float4 bt = *(const float4*)(beta + d);
    float4 z;
    z.x = to_tf32(fmaf(gm.x, (acc.x - mean) * inv, bt.x));
    z.y = to_tf32(fmaf(gm.y, (acc.y - mean) * inv, bt.y));
    z.z = to_tf32(fmaf(gm.z, (acc.z - mean) * inv, bt.z));
    z.w = to_tf32(fmaf(gm.w, (acc.w - mean) * inv, bt.w));
    *(float4*)(g_y + idx) = acc;
    *(float4*)(g_z + idx) = z;
}

// ---------------------------------------------------------------------------
// Kernel 2: wmma tf32 GEMM  [32768 x 512] @ W[512 x 512] (per-half weight)
//   CTA tile 128x128, K-chunk 32, 3-stage cp.async, 1 sync/iter.
//   MODE 0: h = tf32(relu(z @ W1 + b1))
//   MODE 1: x' = y + h @ W2 + b2   (+ strided store to d_out)
// ---------------------------------------------------------------------------
#define BM 128
#define BN 128
#define BK 32
#define ASTRIDE 36
#define BSTRIDE 132
#define CSTRIDE 136
#define A_FLOATS (BM * ASTRIDE)            // 4608
#define B_FLOATS (BK * BSTRIDE)            // 4224
#define STAGE_FLOATS (A_FLOATS + B_FLOATS) // 8832
#define SMEM_FLOATS (3 * STAGE_FLOATS)     // 26496 (Cs 128*136=17408 fits)
#define SMEM_BYTES  (SMEM_FLOATS * 4)      // 105984
#define NCH (DD / BK)                      // 16

template<int MODE>
__global__ void __launch_bounds__(256, 2)
gemm_kernel(int widx_f, int widx_b,
            const float* __restrict__ bias_f,
            const float* __restrict__ bias_b,
            float* __restrict__ outp,
            long long outbase)
{
    extern __shared__ float sm[];
    float* Cs = sm;

    int tid = threadIdx.x;
    int n0 = blockIdx.x * BN;
    int m0 = blockIdx.y * BM;              // global row over 32768
    int half_m = blockIdx.y >> 7;          // 0 fwd, 1 bwd

    const float* __restrict__ A  = (MODE == 0) ? g_z : g_h;
    const float* __restrict__ Wm = g_wt + (size_t)(half_m ? widx_b : widx_f) * DD * DD;
    const float* __restrict__ bias = half_m ? bias_b : bias_f;
    float* __restrict__ C = (MODE == 0) ? g_h : g_state;

    int warp = tid >> 5;
    int warp_m = warp >> 1;
    int warp_n = warp & 1;

    uint32_t sa[3], sb[3];
#pragma unroll
    for (int s = 0; s < 3; s++) {
        sa[s] = smem_u32(sm + s * STAGE_FLOATS);
        sb[s] = smem_u32(sm + s * STAGE_FLOATS + A_FLOATS);
    }

    int arow[4], ac4[4], brow[4], bc4[4];
#pragma unroll
    for (int i = 0; i < 4; i++) {
        int idx = tid + i * 256;
        arow[i] = idx >> 3;  ac4[i] = idx & 7;     // A: 128 rows x 8 float4
        brow[i] = idx >> 5;  bc4[i] = idx & 31;    // B: 32 rows x 32 float4
    }

    wmma::fragment<wmma::accumulator, 16, 16, 8, float> acc[2][4];
#pragma unroll
    for (int i = 0; i < 2; i++)
#pragma unroll
        for (int j = 0; j < 4; j++) wmma::fill_fragment(acc[i][j], 0.f);

    // prologue: prefetch chunks 0 and 1
#pragma unroll
    for (int c = 0; c < 2; c++) {
        int k0 = c * BK;
#pragma unroll
        for (int i = 0; i < 4; i++) {
            cp16(sa[c] + (arow[i] * ASTRIDE + ac4[i] * 4) * 4,
                 A + (size_t)(m0 + arow[i]) * DD + k0 + ac4[i] * 4);
            cp16(sb[c] + (brow[i] * BSTRIDE + bc4[i] * 4) * 4,
                 Wm + (size_t)(k0 + brow[i]) * DD + n0 + bc4[i] * 4);
        }
        CP_COMMIT();
    }

    for (int c = 0; c < NCH; c++) {
        if (c < NCH - 1) { CP_WAIT(1); } else { CP_WAIT(0); }
        __syncthreads();

        // prefetch chunk c+2 into stage (c+2)%3 (buffer finished last iter)
        if (c + 2 < NCH) {
            int st = (c + 2) % 3;
            int k0 = (c + 2) * BK;
#pragma unroll
            for (int i = 0; i < 4; i++) {
                cp16(sa[st] + (arow[i] * ASTRIDE + ac4[i] * 4) * 4,
                     A + (size_t)(m0 + arow[i]) * DD + k0 + ac4[i] * 4);
                cp16(sb[st] + (brow[i] * BSTRIDE + bc4[i] * 4) * 4,
                     Wm + (size_t)(k0 + brow[i]) * DD + n0 + bc4[i] * 4);
            }
            CP_COMMIT();
        }

        const float* Ab = sm + (c % 3) * STAGE_FLOATS;
        const float* Bb = Ab + A_FLOATS;
#pragma unroll
        for (int ks = 0; ks < 4; ks++) {
            wmma::fragment<wmma::matrix_a, 16, 16, 8, wmma::precision::tf32, wmma::row_major> fa[2];
            wmma::fragment<wmma::matrix_b, 16, 16, 8, wmma::precision::tf32, wmma::row_major> fb[4];
#pragma unroll
            for (int i = 0; i < 2; i++)
                wmma::load_matrix_sync(fa[i], Ab + (warp_m * 32 + i * 16) * ASTRIDE + ks * 8, ASTRIDE);
#pragma unroll
            for (int j = 0; j < 4; j++)
                wmma::load_matrix_sync(fb[j], Bb + (ks * 8) * BSTRIDE + warp_n * 64 + j * 16, BSTRIDE);
#pragma unroll
            for (int i = 0; i < 2; i++)
#pragma unroll
                for (int j = 0; j < 4; j++)
                    wmma::mma_sync(acc[i][j], fa[i], fb[j], acc[i][j]);
        }
    }
    __syncthreads();   // all compute done before smem reuse

    // stage accumulators to smem
#pragma unroll
    for (int i = 0; i < 2; i++)
#pragma unroll
        for (int j = 0; j < 4; j++)
            wmma::store_matrix_sync(Cs + (warp_m * 32 + i * 16) * CSTRIDE + warp_n * 64 + j * 16,
                                    acc[i][j], CSTRIDE, wmma::mem_row_major);
    __syncthreads();

    // epilogue: 2 threads per row, 16 float4 each
    int row  = tid >> 1;
    int halfc = tid & 1;
    int grow = m0 + row;                       // global row (0..32767)
    const float* crow = Cs + row * CSTRIDE + halfc * 64;
#pragma unroll
    for (int v = 0; v < 16; v++) {
        int col = n0 + halfc * 64 + v * 4;
        float4 o = *(const float4*)(crow + v * 4);
        float4 bs = *(const float4*)(bias + col);
        o.x += bs.x; o.y += bs.y; o.z += bs.z; o.w += bs.w;
        if (MODE == 0) {
            o.x = to_tf32(fmaxf(o.x, 0.f)); o.y = to_tf32(fmaxf(o.y, 0.f));
            o.z = to_tf32(fmaxf(o.z, 0.f)); o.w = to_tf32(fmaxf(o.w, 0.f));
            *(float4*)(C + (size_t)grow * DD + col) = o;
        } else {
            float4 rv = *(const float4*)(g_y + (size_t)grow * DD + col);
            o.x += rv.x; o.y += rv.y; o.z += rv.z; o.w += rv.w;
            *(float4*)(C + (size_t)grow * DD + col) = o;
            size_t oidx = (size_t)outbase + (size_t)(grow & (NTOK - 1)) * 1024
                        + (half_m ? 512 : 0) + col;
            *(float4*)(outp + oidx) = o;
        }
    }
}

// ---------------------------------------------------------------------------
// Launch: prep + 3 layers x (winln, gemm1, gemm2)  (fwd+bwd merged)
// ---------------------------------------------------------------------------
extern "C" void kernel_launch(void* const* d_in, const int* in_sizes, int n_in,
                              void* d_out, int out_size)
{
    const float* x       = (const float*)d_in[0];
    const float* fwd_pad = (const float*)d_in[1];
    const float* bwd_pad = (const float*)d_in[2];
    const float* fwd_w   = (const float*)d_in[3];
    const float* bwd_w   = (const float*)d_in[4];
    const float* fwd_w1  = (const float*)d_in[5];
    const float* fwd_b1  = (const float*)d_in[6];
    const float* fwd_w2  = (const float*)d_in[7];
    const float* fwd_b2  = (const float*)d_in[8];
    const float* fwd_g   = (const float*)d_in[9];
    const float* fwd_be  = (const float*)d_in[10];
    const float* bwd_w1  = (const float*)d_in[11];
    const float* bwd_b1  = (const float*)d_in[12];
    const float* bwd_w2  = (const float*)d_in[13];
    const float* bwd_b2  = (const float*)d_in[14];
    const float* bwd_g   = (const float*)d_in[15];
    const float* bwd_be  = (const float*)d_in[16];
    float* out = (float*)d_out;

    static int smem_set = 0;
    if (!smem_set) {
        cudaFuncSetAttribute(gemm_kernel<0>, cudaFuncAttributeMaxDynamicSharedMemorySize, SMEM_BYTES);
        cudaFuncSetAttribute(gemm_kernel<1>, cudaFuncAttributeMaxDynamicSharedMemorySize, SMEM_BYTES);
        smem_set = 1;
    }

    prep_kernel<<<dim3(256, 12), 256>>>(fwd_w1, fwd_w2, bwd_w1, bwd_w2);

    dim3 ggrid(4, 256);   // N tiles x M tiles (both halves)

    for (int l = 0; l < 3; l++) {
        const float* pf = fwd_pad + (size_t)l * WW * DD;
        const float* pb = bwd_pad + (size_t)l * WW * DD;
        long long obase = (long long)l * NTOK * 1024;
        int use_x0 = (l == 0) ? 1 : 0;

        winln_kernel<<<2 * NTOK, 128>>>(x, pf, pb,
                                        fwd_w + l * (WW + 1), bwd_w + l * (WW + 1),
                                        fwd_g + l * DD, fwd_be + l * DD,
                                        bwd_g + l * DD, bwd_be + l * DD,
                                        use_x0);
        gemm_kernel<0><<<ggrid, 256, SMEM_BYTES>>>(l * 4 + 0, l * 4 + 2,
                                                   fwd_b1 + l * DD, bwd_b1 + l * DD,
                                                   nullptr, 0);
        gemm_kernel<1><<<ggrid, 256, SMEM_BYTES>>>(l * 4 + 1, l * 4 + 3,
                                                   fwd_b2 + l * DD, bwd_b2 + l * DD,
                                                   out, obase);
    }
}